// round 1
// baseline (speedup 1.0000x reference)
#include <cuda_runtime.h>

#define N 8192
#define NMAT ((size_t)N * (size_t)N)          // 67108864
#define OFF_MASKS (4 * N * 3)                 // 98304
#define OFF_ADJ   (OFF_MASKS + 4 * N)         // 131072

// Voxel grids: dims = ceil(30/v)+1
// L1: vs(0.5,0.5,1.0) -> (61,61,31)
// L2: vs(0.7,0.7,1.2) -> (44,44,26)
// L3: vs(0.9,0.9,1.4) -> (35,35,23)
#define NSEG1 (61 * 61 * 31)   // 115351
#define NSEG2 (44 * 44 * 26)   // 50336
#define NSEG3 (35 * 35 * 23)   // 28175
#define NSEG_TOT (NSEG1 + NSEG2 + NSEG3)

__device__ float g_sx[NSEG_TOT];
__device__ float g_sy[NSEG_TOT];
__device__ float g_sz[NSEG_TOT];
__device__ float g_cn[NSEG_TOT];
__device__ int   g_first[NSEG_TOT];
__device__ float4 g_pts[4][N];   // (x,y,z,valid) per level

__constant__ int   c_la[6] = {0, 1, 2, 1, 2, 3};
__constant__ int   c_lb[6] = {1, 2, 3, 1, 2, 3};
__constant__ float c_r2[6] = {1.0f, 2.25f, 4.0f, 2.25f, 4.0f, 6.25f};

__device__ __forceinline__ int lin_index(int l, float x, float y, float z) {
    if (l == 0) {
        int ix = min(max((int)floorf(x / 0.5f), 0), 60);
        int iy = min(max((int)floorf(y / 0.5f), 0), 60);
        int iz = min(max((int)floorf(z / 1.0f), 0), 30);
        return (ix * 61 + iy) * 31 + iz;
    } else if (l == 1) {
        int ix = min(max((int)floorf(x / 0.7f), 0), 43);
        int iy = min(max((int)floorf(y / 0.7f), 0), 43);
        int iz = min(max((int)floorf(z / 1.2f), 0), 25);
        return NSEG1 + (ix * 44 + iy) * 26 + iz;
    } else {
        int ix = min(max((int)floorf(x / 0.9f), 0), 34);
        int iy = min(max((int)floorf(y / 0.9f), 0), 34);
        int iz = min(max((int)floorf(z / 1.4f), 0), 22);
        return NSEG1 + NSEG2 + (ix * 35 + iy) * 23 + iz;
    }
}

__global__ void k_init() {
    for (int i = blockIdx.x * blockDim.x + threadIdx.x; i < NSEG_TOT;
         i += gridDim.x * blockDim.x) {
        g_sx[i] = 0.0f; g_sy[i] = 0.0f; g_sz[i] = 0.0f; g_cn[i] = 0.0f;
        g_first[i] = 0x7fffffff;
    }
}

__global__ void k_scatter(const float* __restrict__ pts) {
    int i = blockIdx.x * blockDim.x + threadIdx.x;
    if (i >= N) return;
    float x = pts[i * 4 + 0];
    float y = pts[i * 4 + 1];
    float z = pts[i * 4 + 2];
#pragma unroll
    for (int l = 0; l < 3; l++) {
        int lin = lin_index(l, x, y, z);
        atomicAdd(&g_sx[lin], x);
        atomicAdd(&g_sy[lin], y);
        atomicAdd(&g_sz[lin], z);
        atomicAdd(&g_cn[lin], 1.0f);
        atomicMin(&g_first[lin], i);
    }
}

__global__ void k_gather(const float* __restrict__ pts, float* __restrict__ out) {
    int i = blockIdx.x * blockDim.x + threadIdx.x;
    if (i >= N) return;
    float x = pts[i * 4 + 0];
    float y = pts[i * 4 + 1];
    float z = pts[i * 4 + 2];
    g_pts[0][i] = make_float4(x, y, z, 1.0f);
    out[i * 3 + 0] = x;
    out[i * 3 + 1] = y;
    out[i * 3 + 2] = z;
    out[OFF_MASKS + i] = 1.0f;
#pragma unroll
    for (int l = 0; l < 3; l++) {
        int lin = lin_index(l, x, y, z);
        float c  = fmaxf(g_cn[lin], 1.0f);
        float cx = g_sx[lin] / c;
        float cy = g_sy[lin] / c;
        float cz = g_sz[lin] / c;
        bool  m  = (g_first[lin] == i);
        float mf = m ? 1.0f : 0.0f;
        g_pts[l + 1][i] = make_float4(cx, cy, cz, mf);
        size_t co = (size_t)(l + 1) * (N * 3) + (size_t)i * 3;
        out[co + 0] = m ? cx : 0.0f;
        out[co + 1] = m ? cy : 0.0f;
        out[co + 2] = m ? cz : 0.0f;
        out[OFF_MASKS + (l + 1) * N + i] = mf;
    }
}

__device__ __forceinline__ float pairval(float4 a, float4 b, float r2) {
    float dx = a.x - b.x, dy = a.y - b.y, dz = a.z - b.z;
    float d2 = fmaf(dx, dx, fmaf(dy, dy, dz * dz));
    return (d2 <= r2) ? (a.w * b.w) : 0.0f;
}

// 16 (i) x 1024 (j) tile per 256-thread block; 4 j's per thread (float4 store).
__global__ void __launch_bounds__(256) k_adj(float* __restrict__ out) {
    const int mat = blockIdx.z;
    __shared__ float4 sa[16];
    const int   la = c_la[mat];
    const int   lb = c_lb[mat];
    const float r2 = c_r2[mat];
    const bool  diag = (mat >= 3);

    const int i0 = blockIdx.y * 16;
    const int j0 = blockIdx.x * 1024;
    const int t  = threadIdx.x;

    if (t < 16) sa[t] = g_pts[la][i0 + t];
    __syncthreads();

    const int j = j0 + t * 4;
    const float4 b0 = g_pts[lb][j + 0];
    const float4 b1 = g_pts[lb][j + 1];
    const float4 b2 = g_pts[lb][j + 2];
    const float4 b3 = g_pts[lb][j + 3];

    float* obase = out + OFF_ADJ + (size_t)mat * NMAT + (size_t)j;

#pragma unroll
    for (int ii = 0; ii < 16; ii++) {
        float4 a = sa[ii];
        int gi = i0 + ii;
        float4 v;
        v.x = pairval(a, b0, r2);
        v.y = pairval(a, b1, r2);
        v.z = pairval(a, b2, r2);
        v.w = pairval(a, b3, r2);
        if (diag) {
            int d = gi - j;
            if ((unsigned)d < 4u) ((float*)&v)[d] = 0.0f;
        }
        *(float4*)(obase + (size_t)gi * N) = v;
    }
}

extern "C" void kernel_launch(void* const* d_in, const int* in_sizes, int n_in,
                              void* d_out, int out_size) {
    const float* pts = (const float*)d_in[0];
    float* out = (float*)d_out;

    k_init<<<(NSEG_TOT + 255) / 256, 256>>>();
    k_scatter<<<(N + 255) / 256, 256>>>(pts);
    k_gather<<<(N + 255) / 256, 256>>>(pts, out);

    dim3 grid(N / 1024, N / 16, 6);
    k_adj<<<grid, 256>>>(out);
}